// round 16
// baseline (speedup 1.0000x reference)
#include <cuda_runtime.h>
#include <cuda_fp16.h>
#include <math.h>
#include <stdint.h>

// ---------------- problem constants ----------------
#define BATCH 2048
#define FDIM  512
#define MDIM  16
#define HH    32
#define WW    32
#define PD    64
#define KS    11
#define KK    (KS*KS)          // 121
#define HW    (HH*WW)          // 1024
#define SIGMA (11.0f/3.0f)
#define OUT0  (BATCH*576)      // offset of 'updated' in d_out

// ---------------- scratch (static device globals; no allocation) ----------------
__device__ float  g_h1 [BATCH*256];
__device__ float  g_h2 [BATCH*128];
__device__ float  g_wv [BATCH*1936];
__device__ __half g_uph[(size_t)BATCH*HW*16];    // updated, fp16 NHWC (conv1 input)
__device__ __half g_wh1[128*144];                // conv1 W fp16 [oc][tap*16+ic]
__device__ __half g_wh2[9*64*128];               // conv2 W fp16 [tap][oc][ic]
__device__ __half g_y1h[(size_t)BATCH*HW*128];   // conv1 out, NHWC fp16
__device__ float  g_pool[BATCH*576];

// ---------------- mma / ldmatrix / cp.async helpers ----------------
__device__ __forceinline__ void ldsm4(uint32_t* r, const __half* p) {
    uint32_t addr = (uint32_t)__cvta_generic_to_shared(p);
    asm volatile("ldmatrix.sync.aligned.m8n8.x4.shared.b16 {%0,%1,%2,%3}, [%4];\n"
        : "=r"(r[0]), "=r"(r[1]), "=r"(r[2]), "=r"(r[3]) : "r"(addr));
}
__device__ __forceinline__ void mma16816(float* c, const uint32_t* a, uint32_t b0, uint32_t b1) {
    asm volatile("mma.sync.aligned.m16n8k16.row.col.f32.f16.f16.f32 "
        "{%0,%1,%2,%3}, {%4,%5,%6,%7}, {%8,%9}, {%0,%1,%2,%3};\n"
        : "+f"(c[0]), "+f"(c[1]), "+f"(c[2]), "+f"(c[3])
        : "r"(a[0]), "r"(a[1]), "r"(a[2]), "r"(a[3]), "r"(b0), "r"(b1));
}
__device__ __forceinline__ void cpa16(const void* dst, const void* src) {
    uint32_t d = (uint32_t)__cvta_generic_to_shared(dst);
    asm volatile("cp.async.cg.shared.global [%0], [%1], 16;" :: "r"(d), "l"(src));
}
#define CP_COMMIT() asm volatile("cp.async.commit_group;" ::: "memory")
#define CP_WAIT0()  asm volatile("cp.async.wait_group 0;" ::: "memory")

// ======== HGEMM (fp32 in/out, fp16 tensor compute): C = act(A[M,K] @ B[K,N] + bias)
// Block 128M x 64N, K chunk 64. If PE: A = [features | pos_enc(gaze)] computed inline
// (features row stride FDIM; K columns >= FDIM come from the positional encoding).
#define HG_SA 72
template<bool RELU, bool PE>
__global__ void __launch_bounds__(256) hgemm_kernel(const float* __restrict__ A,
                                                    const float* __restrict__ gaze,
                                                    const float* __restrict__ B,
                                                    const float* __restrict__ bias,
                                                    float* __restrict__ C,
                                                    int Kdim, int Ndim) {
    __shared__ __half As[128 * HG_SA];
    __shared__ __half Bs[64 * HG_SA];
    int t = threadIdx.x, lane = t & 31, warp = t >> 5;
    int wm = warp & 3, wn = warp >> 2;
    int row0 = blockIdx.x * 128;
    int col0 = blockIdx.y * 64;

    float acc[2][4][4] = {};
    for (int k0 = 0; k0 < Kdim; k0 += 64) {
        #pragma unroll
        for (int i = 0; i < 32; i++) {
            int idx = t + i * 256;
            int kk = idx & 63, rr = idx >> 6;
            int gk = k0 + kk, grow = row0 + rr;
            float v;
            if (PE) {
                if (gk < FDIM) v = A[(size_t)grow * FDIM + gk];
                else {
                    int jj = gk - FDIM;
                    int axis = jj >> 5, r = jj & 31, di = r >> 1;
                    float d = expf(-(float)(2 * di) * (logf(10000.0f) / 32.0f));
                    float arg = gaze[grow * 2 + axis] * d;
                    v = (r & 1) ? cosf(arg) : sinf(arg);
                }
            } else {
                v = A[(size_t)grow * Kdim + gk];
            }
            As[rr * HG_SA + kk] = __float2half(v);
        }
        #pragma unroll
        for (int i = 0; i < 16; i++) {
            int idx = t + i * 256;
            int nn = idx & 63, kk = idx >> 6;
            int gn = col0 + nn;
            float v = (gn < Ndim) ? B[(size_t)(k0 + kk) * Ndim + gn] : 0.0f;
            Bs[nn * HG_SA + kk] = __float2half(v);
        }
        __syncthreads();
        #pragma unroll
        for (int ks = 0; ks < 4; ks++) {
            uint32_t a[2][4], b[2][4];
            #pragma unroll
            for (int mf = 0; mf < 2; mf++) {
                int row = wm * 32 + mf * 16 + (lane & 15);
                ldsm4(a[mf], As + row * HG_SA + ks * 16 + (lane >> 4) * 8);
            }
            #pragma unroll
            for (int nf2 = 0; nf2 < 2; nf2++) {
                int n = wn * 32 + nf2 * 16 + (lane & 7) + (lane >> 4) * 8;
                ldsm4(b[nf2], Bs + n * HG_SA + ks * 16 + ((lane >> 3) & 1) * 8);
            }
            #pragma unroll
            for (int mf = 0; mf < 2; mf++)
                #pragma unroll
                for (int nf = 0; nf < 4; nf++)
                    mma16816(acc[mf][nf], a[mf],
                             b[nf >> 1][(nf & 1) * 2], b[nf >> 1][(nf & 1) * 2 + 1]);
        }
        __syncthreads();
    }
    #pragma unroll
    for (int mf = 0; mf < 2; mf++) {
        #pragma unroll
        for (int nf = 0; nf < 4; nf++) {
            int px = row0 + wm * 32 + mf * 16 + (lane >> 2);
            int oc = col0 + wn * 32 + nf * 8 + 2 * (lane & 3);
            if (oc < Ndim) {
                float bb0 = bias[oc];
                float v0 = acc[mf][nf][0] + bb0;
                float v2 = acc[mf][nf][2] + bb0;
                if (RELU) { v0 = fmaxf(v0, 0.0f); v2 = fmaxf(v2, 0.0f); }
                C[(size_t)px * Ndim + oc] = v0;
                C[(size_t)(px + 8) * Ndim + oc] = v2;
            }
            if (oc + 1 < Ndim) {
                float bb1 = bias[oc + 1];
                float v1 = acc[mf][nf][1] + bb1;
                float v3 = acc[mf][nf][3] + bb1;
                if (RELU) { v1 = fmaxf(v1, 0.0f); v3 = fmaxf(v3, 0.0f); }
                C[(size_t)px * Ndim + oc + 1] = v1;
                C[(size_t)(px + 8) * Ndim + oc + 1] = v3;
            }
        }
    }
}

// ------- gate + scatter + cell update (256 thr); + conv weight prep + pool zero --
__global__ void gate_scatter_kernel(const float* __restrict__ cell,
                                    const float* __restrict__ gaze,
                                    const float* __restrict__ wv,
                                    const float* __restrict__ ws1,
                                    const float* __restrict__ bs1,
                                    const float* __restrict__ ws2,
                                    const float* __restrict__ bs2,
                                    const float* __restrict__ ck1,
                                    const float* __restrict__ ck2,
                                    __half* __restrict__ wh1,
                                    __half* __restrict__ wh2,
                                    float* __restrict__ pool,
                                    float* __restrict__ updated_out,
                                    __half* __restrict__ updated_h) {
    extern __shared__ float sm[];
    float* num  = sm;                 // 1024*17
    float* den  = sm + 1024 * 17;     // 1024
    float* ws1s = den + 1024;         // 32*64
    float* red  = ws1s + 2048;        // 128
    int b = blockIdx.x, t = threadIdx.x;

    {
        int idx = b * 45 + t;
        if (t < 45) {
            if (idx < 128 * 16 * 9) {
                int oc = idx / 144, rem = idx - oc * 144;
                int ic = rem / 9, tap = rem - ic * 9;
                wh1[oc * 144 + tap * 16 + ic] = __float2half(ck1[idx]);
            } else {
                int i2 = idx - 128 * 16 * 9;
                int oc = i2 / 1152, rem = i2 - oc * 1152;
                int ic = rem / 9, tap = rem - ic * 9;
                wh2[((size_t)tap * 64 + oc) * 128 + ic] = __float2half(ck2[i2]);
            }
        }
        for (int i = t; i < 144; i += 256)
            *(float4*)(pool + (size_t)b * 576 + i * 4) = make_float4(0, 0, 0, 0);
    }

    for (int i = t; i < (1024 * 17 + 1024) / 4; i += 256)
        *(float4*)(sm + i * 4) = make_float4(0, 0, 0, 0);
    for (int i = t; i < 2048; i += 256) ws1s[i] = ws1[i];

    float gx = fminf(fmaxf(gaze[b * 2 + 0] * (WW - 1), 0.0f), (float)(WW - 1));
    float gy = fminf(fmaxf(gaze[b * 2 + 1] * (HH - 1), 0.0f), (float)(HH - 1));
    int x0 = (int)floorf(gx), y0 = (int)floorf(gy);

    int k = t;
    float gauss = 0.0f; int xs = 0, ys = 0;
    if (k < KK) {
        int ox = k % KS - (KS / 2);
        int oy = k / KS - (KS / 2);
        xs = min(max(x0 + ox, 0), WW - 1);
        ys = min(max(y0 + oy, 0), HH - 1);
        float dx = (float)xs - gx, dy = (float)ys - gy;
        gauss = expf(-(dx * dx + dy * dy) / (2.0f * SIGMA * SIGMA));
    }
    if (t < 128) red[t] = gauss;
    __syncthreads();
    for (int s = 64; s > 0; s >>= 1) {
        if (t < s) red[t] += red[t + s];
        __syncthreads();
    }
    float nsum = fmaxf(red[0], 1e-8f);

    if (k < KK) {
        float nw = gauss / nsum;
        int p = ys * WW + xs;
        float prev[MDIM], wval[MDIM];
        const float* cb = cell + (size_t)b * (MDIM * HW);
        #pragma unroll
        for (int m = 0; m < MDIM; m++) prev[m] = cb[m * HW + p];
        const float* wvb = wv + (size_t)b * (KK * MDIM) + k * MDIM;
        #pragma unroll
        for (int m = 0; m < MDIM; m++) wval[m] = wvb[m];

        float acc = bs2[0];
        for (int j = 0; j < 64; j++) {
            float s = bs1[j];
            #pragma unroll
            for (int i = 0; i < MDIM; i++) s += prev[i] * ws1s[i * 64 + j];
            #pragma unroll
            for (int i = 0; i < MDIM; i++) s += wval[i] * ws1s[(MDIM + i) * 64 + j];
            s = fmaxf(s, 0.0f);
            acc += s * ws2[j];
        }
        float gstr = 1.0f / (1.0f + expf(-acc));
        float w = nw * gstr;
        atomicAdd(&den[p], w);
        #pragma unroll
        for (int m = 0; m < MDIM; m++) {
            float nv = (1.0f - w) * prev[m] + w * wval[m];
            atomicAdd(&num[p * 17 + m], w * nv);
        }
    }
    __syncthreads();

    float* uo = updated_out + (size_t)b * (MDIM * HW);
    __half* uh = updated_h + (size_t)b * (HW * MDIM);
    const float* cb = cell + (size_t)b * (MDIM * HW);
    for (int i = t; i < MDIM * HW; i += 256) {
        int p = i & (HW - 1);
        int m = i >> 10;
        float keep = 1.0f - fminf(den[p], 1.0f);
        float v = keep * cb[i] + num[p * 17 + m];
        uo[i] = v;
        uh[p * MDIM + m] = __float2half(v);
    }
}

// ======== conv1 PERSISTENT (per-image): B resident, A-halo double-buffered ======
#define C1_SA   24
#define C1_ZR   192
#define C1_A0o  0
#define C1_A1o  9280
#define C1_Bo   18560
#define C1_BSTR 152
#define C1_OSo  57472                  // 18560 + 128*152*2
#define C1_SMEM (57472 + 34816)        // + 128*136*2 = 92288
__global__ void __launch_bounds__(256, 2) hm_conv1(const __half* __restrict__ uph,
                                                   const __half* __restrict__ wh,
                                                   const float* __restrict__ bias,
                                                   __half* __restrict__ out) {
    extern __shared__ char smraw[];
    __half* Bs = (__half*)(smraw + C1_Bo);
    __half* Os = (__half*)(smraw + C1_OSo);
    int tid = threadIdx.x, lane = tid & 31, warp = tid >> 5;
    int wm = warp & 3, wn = warp >> 2;
    int img = blockIdx.x;
    const __half* inb = uph + (size_t)img * HW * 16;

    #pragma unroll
    for (int i = 0; i < 9; i++) {
        int idx = tid + i * 256;
        int row = idx / 18, c = idx - row * 18;
        cpa16(Bs + row * C1_BSTR + c * 8, wh + (size_t)row * 144 + c * 8);
    }
    {
        __half* A0 = (__half*)(smraw + C1_A0o);
        #pragma unroll
        for (int i = 0; i < 2; i++) {
            int idx = tid + i * 256;
            if (idx < 386) {
                int hr = idx >> 1, c = idx & 1;
                int sy = -1 + (hr >> 5), sx = hr & 31;
                if (hr < 192 && sy >= 0)
                    cpa16(A0 + hr * C1_SA + c * 8, inb + (size_t)(sy * 32 + sx) * 16 + c * 8);
                else
                    *(uint4*)(A0 + hr * C1_SA + c * 8) = make_uint4(0, 0, 0, 0);
            }
        }
    }
    CP_COMMIT(); CP_WAIT0(); __syncthreads();

    for (int s = 0; s < 8; s++) {
        __half* Acur = (__half*)(smraw + ((s & 1) ? C1_A1o : C1_A0o));
        if (s < 7) {
            __half* An = (__half*)(smraw + ((s & 1) ? C1_A0o : C1_A1o));
            int ys = (s + 1) * 4;
            #pragma unroll
            for (int i = 0; i < 2; i++) {
                int idx = tid + i * 256;
                if (idx < 386) {
                    int hr = idx >> 1, c = idx & 1;
                    int sy = ys - 1 + (hr >> 5), sx = hr & 31;
                    if (hr < 192 && sy >= 0 && sy < HH)
                        cpa16(An + hr * C1_SA + c * 8, inb + (size_t)(sy * 32 + sx) * 16 + c * 8);
                    else
                        *(uint4*)(An + hr * C1_SA + c * 8) = make_uint4(0, 0, 0, 0);
                }
            }
            CP_COMMIT();
        }
        int y0 = s * 4;
        float acc[2][8][4] = {};
        #pragma unroll
        for (int tap = 0; tap < 9; tap++) {
            int dy = tap / 3 - 1, dx = tap % 3 - 1;
            uint32_t a[2][4], b[4][4];
            #pragma unroll
            for (int mf = 0; mf < 2; mf++) {
                int p = wm * 32 + mf * 16 + (lane & 15);
                int py = p >> 5, px_ = p & 31;
                int sy = y0 + py + dy, sx = px_ + dx;
                int hr = ((unsigned)sy < (unsigned)HH && (unsigned)sx < (unsigned)WW)
                       ? (py + dy + 1) * 32 + sx : C1_ZR;
                ldsm4(a[mf], Acur + hr * C1_SA + (lane >> 4) * 8);
            }
            #pragma unroll
            for (int nf2 = 0; nf2 < 4; nf2++) {
                int n = wn * 64 + nf2 * 16 + (lane & 7) + (lane >> 4) * 8;
                int col = tap * 16 + ((lane >> 3) & 1) * 8;
                ldsm4(b[nf2], Bs + n * C1_BSTR + col);
            }
            #pragma unroll
            for (int mf = 0; mf < 2; mf++)
                #pragma unroll
                for (int nf = 0; nf < 8; nf++)
                    mma16816(acc[mf][nf], a[mf], b[nf >> 1][(nf & 1) * 2], b[nf >> 1][(nf & 1) * 2 + 1]);
        }

        #pragma unroll
        for (int mf = 0; mf < 2; mf++) {
            #pragma unroll
            for (int nf = 0; nf < 8; nf++) {
                int px = wm * 32 + mf * 16 + (lane >> 2);
                int oc = wn * 64 + nf * 8 + 2 * (lane & 3);
                float bb0 = bias[oc], bb1 = bias[oc + 1];
                float v0 = fmaxf(acc[mf][nf][0] + bb0, 0.0f);
                float v1 = fmaxf(acc[mf][nf][1] + bb1, 0.0f);
                *(__half2*)(Os + px * 136 + oc) = __floats2half2_rn(v0, v1);
                v0 = fmaxf(acc[mf][nf][2] + bb0, 0.0f);
                v1 = fmaxf(acc[mf][nf][3] + bb1, 0.0f);
                *(__half2*)(Os + (px + 8) * 136 + oc) = __floats2half2_rn(v0, v1);
            }
        }
        __syncthreads();
        __half* ob = out + (size_t)img * HW * 128 + (size_t)s * 128 * 128;
        #pragma unroll
        for (int i = 0; i < 8; i++) {
            int idx = tid + i * 256;
            int p = idx >> 4, ch = idx & 15;
            *(uint4*)(ob + (size_t)p * 128 + ch * 8) = *(uint4*)(Os + p * 136 + ch * 8);
        }
        CP_WAIT0();
        __syncthreads();
    }
}

// == conv2: swizzled A (stride 256) + cp.async double-buffered B; 2 blocks/SM ====
#define C2_ZR   320
#define C2_B0o  82176
#define C2_B1o  (82176 + 16384)
#define C2_SMEM (82176 + 32768)        // 114944 -> 2 blocks/SM
__device__ __forceinline__ uint32_t c2sw(int row, int chunk) {
    return (uint32_t)(row * 256 + ((chunk ^ (row & 7)) << 4));
}
__global__ void __launch_bounds__(256, 2) hm_conv2(const __half* __restrict__ y1,
                                                   const __half* __restrict__ wh,
                                                   const float* __restrict__ bias,
                                                   float* __restrict__ pool) {
    extern __shared__ char smraw[];
    char* As = smraw;
    int tid = threadIdx.x, lane = tid & 31, warp = tid >> 5;
    int wm = warp & 3, wn = warp >> 2;   // 4M x 2N; warp tile 64px x 32oc
    int img = blockIdx.x;
    const __half* inb = y1 + (size_t)img * HW * 128;

    for (int i = 0; i < 21; i++) {
        int idx = tid + i * 256;
        if (idx < 321 * 16) {
            int hr = idx >> 4, c = idx & 15;
            int sy = -1 + (hr >> 5), sx = hr & 31;
            if (hr < 320 && sy >= 0)
                cpa16(As + c2sw(hr, c), inb + (size_t)(sy * 32 + sx) * 128 + c * 8);
            else
                *(uint4*)(As + c2sw(hr, c)) = make_uint4(0, 0, 0, 0);
        }
    }
    #pragma unroll
    for (int i = 0; i < 4; i++) {
        int idx = tid + i * 256;
        int row = idx >> 4, c = idx & 15;
        cpa16(smraw + C2_B0o + c2sw(row, c), wh + (size_t)row * 128 + c * 8);
    }
    CP_COMMIT(); CP_WAIT0(); __syncthreads();

    for (int q = 0; q < 4; q++) {
        float acc[4][4][4] = {};
        for (int tap = 0; tap < 9; tap++) {
            int k = q * 9 + tap;
            bool pf = (k < 35);
            if (pf) {
                int tn = (tap + 1) % 9;
                char* Bn = smraw + (((k + 1) & 1) ? C2_B1o : C2_B0o);
                const __half* wb = wh + (size_t)tn * 64 * 128;
                #pragma unroll
                for (int i = 0; i < 4; i++) {
                    int idx = tid + i * 256;
                    int row = idx >> 4, c = idx & 15;
                    cpa16(Bn + c2sw(row, c), wb + (size_t)row * 128 + c * 8);
                }
                CP_COMMIT();
            }
            char* Bcur = smraw + ((k & 1) ? C2_B1o : C2_B0o);
            int dy = tap / 3 - 1, dx = tap % 3 - 1;
            int hrow[4];
            #pragma unroll
            for (int mf = 0; mf < 4; mf++) {
                int p = wm * 64 + mf * 16 + (lane & 15);
                int py = p >> 5, px_ = p & 31;
                int sy = q * 8 + py + dy, sx = px_ + dx;
                hrow[mf] = ((unsigned)sy < (unsigned)HH && (unsigned)sx < (unsigned)WW)
                         ? (py + dy + 1) * 32 + sx : C2_ZR;
            }
            #pragma unroll
            for (int ks = 0; ks < 8; ks++) {
                uint32_t a[4][4], b[2][4];
                #pragma unroll
                for (int mf = 0; mf < 4; mf++)
                    ldsm4(a[mf], (const __half*)(As + c2sw(hrow[mf], ks * 2 + (lane >> 4))));
                #pragma unroll
                for (int nf2 = 0; nf2 < 2; nf2++) {
                    int n = wn * 32 + nf2 * 16 + (lane & 7) + (lane >> 4) * 8;
                    ldsm4(b[nf2], (const __half*)(Bcur + c2sw(n, ks * 2 + ((lane >> 3) & 1))));
                }
                #pragma unroll
                for (int mf = 0; mf < 4; mf++)
                    #pragma unroll
                    for (int nf = 0; nf < 4; nf++)
                        mma16816(acc[mf][nf], a[mf],
                                 b[nf >> 1][(nf & 1) * 2], b[nf >> 1][(nf & 1) * 2 + 1]);
            }
            if (pf) { CP_WAIT0(); }
            __syncthreads();
        }

        __half* os = (__half*)As;
        #pragma unroll
        for (int mf = 0; mf < 4; mf++) {
            #pragma unroll
            for (int nf = 0; nf < 4; nf++) {
                int px = wm * 64 + mf * 16 + (lane >> 2);
                int oc = wn * 32 + nf * 8 + 2 * (lane & 3);
                float bb0 = bias[oc], bb1 = bias[oc + 1];
                float v0 = fmaxf(acc[mf][nf][0] + bb0, 0.0f);
                float v1 = fmaxf(acc[mf][nf][1] + bb1, 0.0f);
                *(__half2*)(os + px * 80 + oc) = __floats2half2_rn(v0, v1);
                v0 = fmaxf(acc[mf][nf][2] + bb0, 0.0f);
                v1 = fmaxf(acc[mf][nf][3] + bb1, 0.0f);
                *(__half2*)(os + (px + 8) * 80 + oc) = __floats2half2_rn(v0, v1);
            }
        }
        __syncthreads();

        if (tid < 192) {
            int j = tid >> 6, c = tid & 63;
            int w0 = (j == 0) ? 0 : (j == 1 ? 10 : 21);
            int w1_ = (j == 0) ? 11 : (j == 1 ? 22 : 32);
            float cs0 = 0.0f, cs1 = 0.0f, cs2 = 0.0f;
            #pragma unroll
            for (int r = 0; r < 8; r++) {
                int y = q * 8 + r;
                float rs = 0.0f;
                for (int x = w0; x < w1_; x++) rs += __half2float(os[(r * 32 + x) * 80 + c]);
                if (y < 11) cs0 += rs;
                if (y >= 10 && y < 22) cs1 += rs;
                if (y >= 21) cs2 += rs;
            }
            float wsz = (float)(w1_ - w0);
            float* pb = pool + (size_t)img * 576 + c * 9 + j;
            if (q <= 1)           atomicAdd(pb + 0, cs0 / (11.0f * wsz));
            if (q == 1 || q == 2) atomicAdd(pb + 3, cs1 / (12.0f * wsz));
            if (q >= 2)           atomicAdd(pb + 6, cs2 / (11.0f * wsz));
        }
        __syncthreads();

        if (q < 3) {
            for (int i = 0; i < 21; i++) {
                int idx = tid + i * 256;
                if (idx < 321 * 16) {
                    int hr = idx >> 4, c = idx & 15;
                    int sy = (q + 1) * 8 - 1 + (hr >> 5), sx = hr & 31;
                    if (hr < 320 && sy >= 0 && sy < HH)
                        cpa16(As + c2sw(hr, c), inb + (size_t)(sy * 32 + sx) * 128 + c * 8);
                    else
                        *(uint4*)(As + c2sw(hr, c)) = make_uint4(0, 0, 0, 0);
                }
            }
            CP_COMMIT(); CP_WAIT0(); __syncthreads();
        }
    }
}

// ---------------- launch ----------------
extern "C" void kernel_launch(void* const* d_in, const int* in_sizes, int n_in,
                              void* d_out, int out_size) {
    const float* features = (const float*)d_in[0];
    const float* cell     = (const float*)d_in[1];
    const float* gaze     = (const float*)d_in[2];
    const float* w1  = (const float*)d_in[3];
    const float* b1  = (const float*)d_in[4];
    const float* w2  = (const float*)d_in[5];
    const float* b2  = (const float*)d_in[6];
    const float* wvw = (const float*)d_in[7];
    const float* bv  = (const float*)d_in[8];
    const float* ws1 = (const float*)d_in[9];
    const float* bs1 = (const float*)d_in[10];
    const float* ws2 = (const float*)d_in[11];
    const float* bs2 = (const float*)d_in[12];
    const float* ck1 = (const float*)d_in[13];
    const float* cb1 = (const float*)d_in[14];
    const float* ck2 = (const float*)d_in[15];
    const float* cb2 = (const float*)d_in[16];
    const float* wo  = (const float*)d_in[17];
    const float* bo  = (const float*)d_in[18];

    float* out = (float*)d_out;
    float* updated = out + OUT0;

    float *ph1, *ph2, *pwv, *ppool;
    __half *puph, *pwh1, *pwh2, *py1h;
    cudaGetSymbolAddress((void**)&ph1,  g_h1);
    cudaGetSymbolAddress((void**)&ph2,  g_h2);
    cudaGetSymbolAddress((void**)&pwv,  g_wv);
    cudaGetSymbolAddress((void**)&puph, g_uph);
    cudaGetSymbolAddress((void**)&pwh1, g_wh1);
    cudaGetSymbolAddress((void**)&pwh2, g_wh2);
    cudaGetSymbolAddress((void**)&py1h, g_y1h);
    cudaGetSymbolAddress((void**)&ppool,g_pool);

    // 1) MLP1 (x=[features|PE] -> 256, relu) via HMMA with inline PE
    {
        dim3 g(BATCH / 128, 256 / 64);
        hgemm_kernel<true, true><<<g, 256>>>(features, gaze, w1, b1, ph1, 576, 256);
    }
    // 2) MLP2 (256 -> 128, relu) via HMMA
    {
        dim3 g(BATCH / 128, 128 / 64);
        hgemm_kernel<true, false><<<g, 256>>>(ph1, gaze, w2, b2, ph2, 256, 128);
    }
    // 3) write-values GEMM (128 -> 1936) via HMMA
    {
        dim3 g(BATCH / 128, (1936 + 63) / 64);
        hgemm_kernel<false, false><<<g, 256>>>(ph2, gaze, wvw, bv, pwv, 128, 1936);
    }

    // 4) gate + scatter (+ weight prep + pool zero) -> updated + fp16 copy
    {
        size_t smem = (size_t)(1024 * 17 + 1024 + 2048 + 128) * sizeof(float);
        cudaFuncSetAttribute(gate_scatter_kernel,
                             cudaFuncAttributeMaxDynamicSharedMemorySize, (int)smem);
        gate_scatter_kernel<<<BATCH, 256, smem>>>(cell, gaze, pwv, ws1, bs1, ws2, bs2,
                                                  ck1, ck2, pwh1, pwh2, ppool,
                                                  updated, puph);
    }

    // 5) conv1 persistent (per image)
    {
        cudaFuncSetAttribute(hm_conv1, cudaFuncAttributeMaxDynamicSharedMemorySize, C1_SMEM);
        hm_conv1<<<BATCH, 256, C1_SMEM>>>(puph, pwh1, cb1, py1h);
    }
    // 6) conv2: swizzled A + async-double-buffered B, 2 blocks/SM, fused pool
    {
        cudaFuncSetAttribute(hm_conv2, cudaFuncAttributeMaxDynamicSharedMemorySize, C2_SMEM);
        hm_conv2<<<BATCH, 256, C2_SMEM>>>(py1h, pwh2, cb2, ppool);
    }

    // 7) final linear (576 -> 576) via HMMA
    {
        dim3 g(BATCH / 128, 576 / 64);
        hgemm_kernel<false, false><<<g, 256>>>(ppool, gaze, wo, bo, out, 576, 576);
    }
}

// round 17
// speedup vs baseline: 1.1671x; 1.1671x over previous
#include <cuda_runtime.h>
#include <cuda_fp16.h>
#include <math.h>
#include <stdint.h>

// ---------------- problem constants ----------------
#define BATCH 2048
#define FDIM  512
#define MDIM  16
#define HH    32
#define WW    32
#define PD    64
#define KS    11
#define KK    (KS*KS)          // 121
#define HW    (HH*WW)          // 1024
#define SIGMA (11.0f/3.0f)
#define OUT0  (BATCH*576)      // offset of 'updated' in d_out

// ---------------- scratch (static device globals; no allocation) ----------------
__device__ float  g_x  [BATCH*576];
__device__ float  g_h1 [BATCH*256];
__device__ float  g_h2 [BATCH*128];
__device__ float  g_wv [BATCH*1936];
__device__ __half g_uph[(size_t)BATCH*HW*16];    // updated, fp16 NHWC (conv1 input)
__device__ __half g_wh1[128*144];                // conv1 W fp16 [oc][tap*16+ic]
__device__ __half g_wh2[9*64*128];               // conv2 W fp16 [tap][oc][ic]
__device__ __half g_y1h[(size_t)BATCH*HW*128];   // conv1 out, NHWC fp16
__device__ float  g_pool[BATCH*576];

// ---------------- mma / ldmatrix / cp.async helpers ----------------
__device__ __forceinline__ void ldsm4(uint32_t* r, const __half* p) {
    uint32_t addr = (uint32_t)__cvta_generic_to_shared(p);
    asm volatile("ldmatrix.sync.aligned.m8n8.x4.shared.b16 {%0,%1,%2,%3}, [%4];\n"
        : "=r"(r[0]), "=r"(r[1]), "=r"(r[2]), "=r"(r[3]) : "r"(addr));
}
__device__ __forceinline__ void mma16816(float* c, const uint32_t* a, uint32_t b0, uint32_t b1) {
    asm volatile("mma.sync.aligned.m16n8k16.row.col.f32.f16.f16.f32 "
        "{%0,%1,%2,%3}, {%4,%5,%6,%7}, {%8,%9}, {%0,%1,%2,%3};\n"
        : "+f"(c[0]), "+f"(c[1]), "+f"(c[2]), "+f"(c[3])
        : "r"(a[0]), "r"(a[1]), "r"(a[2]), "r"(a[3]), "r"(b0), "r"(b1));
}
__device__ __forceinline__ void cpa16(const void* dst, const void* src) {
    uint32_t d = (uint32_t)__cvta_generic_to_shared(dst);
    asm volatile("cp.async.cg.shared.global [%0], [%1], 16;" :: "r"(d), "l"(src));
}
#define CP_COMMIT() asm volatile("cp.async.commit_group;" ::: "memory")
#define CP_WAIT0()  asm volatile("cp.async.wait_group 0;" ::: "memory")

// ---------------- build x = concat(features, pos_encoding(gaze)) ----------------
__global__ void build_x_kernel(const float* __restrict__ features,
                               const float* __restrict__ gaze,
                               float* __restrict__ x) {
    int idx = blockIdx.x * blockDim.x + threadIdx.x;
    if (idx >= BATCH * 576) return;
    int b = idx / 576, j = idx % 576;
    if (j < FDIM) { x[idx] = features[(size_t)b * FDIM + j]; return; }
    int jj = j - FDIM;
    int axis = jj >> 5;
    int r = jj & 31;
    int di = r >> 1;
    float d = expf(-(float)(2 * di) * (logf(10000.0f) / 32.0f));
    float arg = gaze[b * 2 + axis] * d;
    x[idx] = (r & 1) ? cosf(arg) : sinf(arg);
}

// ======== HGEMM (fp32 in/out, fp16 tensor compute): C = act(A[M,K] @ B[K,N] + bias)
#define HG_SA 72
template<bool RELU>
__global__ void __launch_bounds__(256) hgemm_kernel(const float* __restrict__ A,
                                                    const float* __restrict__ B,
                                                    const float* __restrict__ bias,
                                                    float* __restrict__ C,
                                                    int Kdim, int Ndim) {
    __shared__ __half As[128 * HG_SA];
    __shared__ __half Bs[64 * HG_SA];
    int t = threadIdx.x, lane = t & 31, warp = t >> 5;
    int wm = warp & 3, wn = warp >> 2;
    int row0 = blockIdx.x * 128;
    int col0 = blockIdx.y * 64;

    float acc[2][4][4] = {};
    for (int k0 = 0; k0 < Kdim; k0 += 64) {
        #pragma unroll
        for (int i = 0; i < 32; i++) {
            int idx = t + i * 256;
            int kk = idx & 63, rr = idx >> 6;
            As[rr * HG_SA + kk] = __float2half(A[(size_t)(row0 + rr) * Kdim + k0 + kk]);
        }
        #pragma unroll
        for (int i = 0; i < 16; i++) {
            int idx = t + i * 256;
            int nn = idx & 63, kk = idx >> 6;
            int gn = col0 + nn;
            float v = (gn < Ndim) ? B[(size_t)(k0 + kk) * Ndim + gn] : 0.0f;
            Bs[nn * HG_SA + kk] = __float2half(v);
        }
        __syncthreads();
        #pragma unroll
        for (int ks = 0; ks < 4; ks++) {
            uint32_t a[2][4], b[2][4];
            #pragma unroll
            for (int mf = 0; mf < 2; mf++) {
                int row = wm * 32 + mf * 16 + (lane & 15);
                ldsm4(a[mf], As + row * HG_SA + ks * 16 + (lane >> 4) * 8);
            }
            #pragma unroll
            for (int nf2 = 0; nf2 < 2; nf2++) {
                int n = wn * 32 + nf2 * 16 + (lane & 7) + (lane >> 4) * 8;
                ldsm4(b[nf2], Bs + n * HG_SA + ks * 16 + ((lane >> 3) & 1) * 8);
            }
            #pragma unroll
            for (int mf = 0; mf < 2; mf++)
                #pragma unroll
                for (int nf = 0; nf < 4; nf++)
                    mma16816(acc[mf][nf], a[mf],
                             b[nf >> 1][(nf & 1) * 2], b[nf >> 1][(nf & 1) * 2 + 1]);
        }
        __syncthreads();
    }
    #pragma unroll
    for (int mf = 0; mf < 2; mf++) {
        #pragma unroll
        for (int nf = 0; nf < 4; nf++) {
            int px = row0 + wm * 32 + mf * 16 + (lane >> 2);
            int oc = col0 + wn * 32 + nf * 8 + 2 * (lane & 3);
            if (oc < Ndim) {
                float bb0 = bias[oc];
                float v0 = acc[mf][nf][0] + bb0;
                float v2 = acc[mf][nf][2] + bb0;
                if (RELU) { v0 = fmaxf(v0, 0.0f); v2 = fmaxf(v2, 0.0f); }
                C[(size_t)px * Ndim + oc] = v0;
                C[(size_t)(px + 8) * Ndim + oc] = v2;
            }
            if (oc + 1 < Ndim) {
                float bb1 = bias[oc + 1];
                float v1 = acc[mf][nf][1] + bb1;
                float v3 = acc[mf][nf][3] + bb1;
                if (RELU) { v1 = fmaxf(v1, 0.0f); v3 = fmaxf(v3, 0.0f); }
                C[(size_t)px * Ndim + oc + 1] = v1;
                C[(size_t)(px + 8) * Ndim + oc + 1] = v3;
            }
        }
    }
}

// ------- gate + scatter + cell update (256 thr); + conv weight prep + pool zero --
__global__ void gate_scatter_kernel(const float* __restrict__ cell,
                                    const float* __restrict__ gaze,
                                    const float* __restrict__ wv,
                                    const float* __restrict__ ws1,
                                    const float* __restrict__ bs1,
                                    const float* __restrict__ ws2,
                                    const float* __restrict__ bs2,
                                    const float* __restrict__ ck1,
                                    const float* __restrict__ ck2,
                                    __half* __restrict__ wh1,
                                    __half* __restrict__ wh2,
                                    float* __restrict__ pool,
                                    float* __restrict__ updated_out,
                                    __half* __restrict__ updated_h) {
    extern __shared__ float sm[];
    float* num  = sm;                 // 1024*17
    float* den  = sm + 1024 * 17;     // 1024
    float* ws1s = den + 1024;         // 32*64
    float* red  = ws1s + 2048;        // 128
    int b = blockIdx.x, t = threadIdx.x;

    {
        int idx = b * 45 + t;
        if (t < 45) {
            if (idx < 128 * 16 * 9) {
                int oc = idx / 144, rem = idx - oc * 144;
                int ic = rem / 9, tap = rem - ic * 9;
                wh1[oc * 144 + tap * 16 + ic] = __float2half(ck1[idx]);
            } else {
                int i2 = idx - 128 * 16 * 9;
                int oc = i2 / 1152, rem = i2 - oc * 1152;
                int ic = rem / 9, tap = rem - ic * 9;
                wh2[((size_t)tap * 64 + oc) * 128 + ic] = __float2half(ck2[i2]);
            }
        }
        for (int i = t; i < 576; i += 256) pool[(size_t)b * 576 + i] = 0.0f;
    }

    for (int i = t; i < 1024 * 17 + 1024; i += 256) sm[i] = 0.0f;
    for (int i = t; i < 2048; i += 256) ws1s[i] = ws1[i];

    float gx = fminf(fmaxf(gaze[b * 2 + 0] * (WW - 1), 0.0f), (float)(WW - 1));
    float gy = fminf(fmaxf(gaze[b * 2 + 1] * (HH - 1), 0.0f), (float)(HH - 1));
    int x0 = (int)floorf(gx), y0 = (int)floorf(gy);

    int k = t;
    float gauss = 0.0f; int xs = 0, ys = 0;
    if (k < KK) {
        int ox = k % KS - (KS / 2);
        int oy = k / KS - (KS / 2);
        xs = min(max(x0 + ox, 0), WW - 1);
        ys = min(max(y0 + oy, 0), HH - 1);
        float dx = (float)xs - gx, dy = (float)ys - gy;
        gauss = expf(-(dx * dx + dy * dy) / (2.0f * SIGMA * SIGMA));
    }
    if (t < 128) red[t] = gauss;
    __syncthreads();
    for (int s = 64; s > 0; s >>= 1) {
        if (t < s) red[t] += red[t + s];
        __syncthreads();
    }
    float nsum = fmaxf(red[0], 1e-8f);

    if (k < KK) {
        float nw = gauss / nsum;
        int p = ys * WW + xs;
        float prev[MDIM], wval[MDIM];
        const float* cb = cell + (size_t)b * (MDIM * HW);
        #pragma unroll
        for (int m = 0; m < MDIM; m++) prev[m] = cb[m * HW + p];
        const float* wvb = wv + (size_t)b * (KK * MDIM) + k * MDIM;
        #pragma unroll
        for (int m = 0; m < MDIM; m++) wval[m] = wvb[m];

        float acc = bs2[0];
        for (int j = 0; j < 64; j++) {
            float s = bs1[j];
            #pragma unroll
            for (int i = 0; i < MDIM; i++) s += prev[i] * ws1s[i * 64 + j];
            #pragma unroll
            for (int i = 0; i < MDIM; i++) s += wval[i] * ws1s[(MDIM + i) * 64 + j];
            s = fmaxf(s, 0.0f);
            acc += s * ws2[j];
        }
        float gstr = 1.0f / (1.0f + expf(-acc));
        float w = nw * gstr;
        atomicAdd(&den[p], w);
        #pragma unroll
        for (int m = 0; m < MDIM; m++) {
            float nv = (1.0f - w) * prev[m] + w * wval[m];
            atomicAdd(&num[p * 17 + m], w * nv);
        }
    }
    __syncthreads();

    // phase 1: NCHW coalesced read/write; stash v back into the consumed num slot
    float* uo = updated_out + (size_t)b * (MDIM * HW);
    __half* uh = updated_h + (size_t)b * (HW * MDIM);
    const float* cb = cell + (size_t)b * (MDIM * HW);
    for (int i = t; i < MDIM * HW; i += 256) {
        int p = i & (HW - 1);
        int m = i >> 10;
        float keep = 1.0f - fminf(den[p], 1.0f);
        float v = keep * cb[i] + num[p * 17 + m];
        uo[i] = v;
        num[p * 17 + m] = v;                       // stash for coalesced NHWC pass
    }
    __syncthreads();
    // phase 2: NHWC fp16 write, 8 halves -> one uint4 per thread-iter (coalesced)
    for (int j = t; j < (MDIM * HW) / 8; j += 256) {
        int base = j * 8;
        __half tmp[8];
        #pragma unroll
        for (int e = 0; e < 8; e++) {
            int idx = base + e;
            int p = idx >> 4, m = idx & 15;
            tmp[e] = __float2half(num[p * 17 + m]);
        }
        *(uint4*)(uh + base) = *(uint4*)tmp;
    }
}

// ======== conv1 PERSISTENT (per-image): B resident, A-halo double-buffered ======
#define C1_SA   24
#define C1_ZR   192
#define C1_A0o  0
#define C1_A1o  9280
#define C1_Bo   18560
#define C1_BSTR 152
#define C1_OSo  57472                  // 18560 + 128*152*2
#define C1_SMEM (57472 + 34816)        // + 128*136*2 = 92288
__global__ void __launch_bounds__(256, 2) hm_conv1(const __half* __restrict__ uph,
                                                   const __half* __restrict__ wh,
                                                   const float* __restrict__ bias,
                                                   __half* __restrict__ out) {
    extern __shared__ char smraw[];
    __half* Bs = (__half*)(smraw + C1_Bo);
    __half* Os = (__half*)(smraw + C1_OSo);
    int tid = threadIdx.x, lane = tid & 31, warp = tid >> 5;
    int wm = warp & 3, wn = warp >> 2;
    int img = blockIdx.x;
    const __half* inb = uph + (size_t)img * HW * 16;

    #pragma unroll
    for (int i = 0; i < 9; i++) {
        int idx = tid + i * 256;
        int row = idx / 18, c = idx - row * 18;
        cpa16(Bs + row * C1_BSTR + c * 8, wh + (size_t)row * 144 + c * 8);
    }
    {
        __half* A0 = (__half*)(smraw + C1_A0o);
        #pragma unroll
        for (int i = 0; i < 2; i++) {
            int idx = tid + i * 256;
            if (idx < 386) {
                int hr = idx >> 1, c = idx & 1;
                int sy = -1 + (hr >> 5), sx = hr & 31;
                if (hr < 192 && sy >= 0)
                    cpa16(A0 + hr * C1_SA + c * 8, inb + (size_t)(sy * 32 + sx) * 16 + c * 8);
                else
                    *(uint4*)(A0 + hr * C1_SA + c * 8) = make_uint4(0, 0, 0, 0);
            }
        }
    }
    CP_COMMIT(); CP_WAIT0(); __syncthreads();

    for (int s = 0; s < 8; s++) {
        __half* Acur = (__half*)(smraw + ((s & 1) ? C1_A1o : C1_A0o));
        if (s < 7) {
            __half* An = (__half*)(smraw + ((s & 1) ? C1_A0o : C1_A1o));
            int ys = (s + 1) * 4;
            #pragma unroll
            for (int i = 0; i < 2; i++) {
                int idx = tid + i * 256;
                if (idx < 386) {
                    int hr = idx >> 1, c = idx & 1;
                    int sy = ys - 1 + (hr >> 5), sx = hr & 31;
                    if (hr < 192 && sy >= 0 && sy < HH)
                        cpa16(An + hr * C1_SA + c * 8, inb + (size_t)(sy * 32 + sx) * 16 + c * 8);
                    else
                        *(uint4*)(An + hr * C1_SA + c * 8) = make_uint4(0, 0, 0, 0);
                }
            }
            CP_COMMIT();
        }
        int y0 = s * 4;
        float acc[2][8][4] = {};
        #pragma unroll
        for (int tap = 0; tap < 9; tap++) {
            int dy = tap / 3 - 1, dx = tap % 3 - 1;
            uint32_t a[2][4], b[4][4];
            #pragma unroll
            for (int mf = 0; mf < 2; mf++) {
                int p = wm * 32 + mf * 16 + (lane & 15);
                int py = p >> 5, px_ = p & 31;
                int sy = y0 + py + dy, sx = px_ + dx;
                int hr = ((unsigned)sy < (unsigned)HH && (unsigned)sx < (unsigned)WW)
                       ? (py + dy + 1) * 32 + sx : C1_ZR;
                ldsm4(a[mf], Acur + hr * C1_SA + (lane >> 4) * 8);
            }
            #pragma unroll
            for (int nf2 = 0; nf2 < 4; nf2++) {
                int n = wn * 64 + nf2 * 16 + (lane & 7) + (lane >> 4) * 8;
                int col = tap * 16 + ((lane >> 3) & 1) * 8;
                ldsm4(b[nf2], Bs + n * C1_BSTR + col);
            }
            #pragma unroll
            for (int mf = 0; mf < 2; mf++)
                #pragma unroll
                for (int nf = 0; nf < 8; nf++)
                    mma16816(acc[mf][nf], a[mf], b[nf >> 1][(nf & 1) * 2], b[nf >> 1][(nf & 1) * 2 + 1]);
        }

        #pragma unroll
        for (int mf = 0; mf < 2; mf++) {
            #pragma unroll
            for (int nf = 0; nf < 8; nf++) {
                int px = wm * 32 + mf * 16 + (lane >> 2);
                int oc = wn * 64 + nf * 8 + 2 * (lane & 3);
                float bb0 = bias[oc], bb1 = bias[oc + 1];
                float v0 = fmaxf(acc[mf][nf][0] + bb0, 0.0f);
                float v1 = fmaxf(acc[mf][nf][1] + bb1, 0.0f);
                *(__half2*)(Os + px * 136 + oc) = __floats2half2_rn(v0, v1);
                v0 = fmaxf(acc[mf][nf][2] + bb0, 0.0f);
                v1 = fmaxf(acc[mf][nf][3] + bb1, 0.0f);
                *(__half2*)(Os + (px + 8) * 136 + oc) = __floats2half2_rn(v0, v1);
            }
        }
        __syncthreads();
        __half* ob = out + (size_t)img * HW * 128 + (size_t)s * 128 * 128;
        #pragma unroll
        for (int i = 0; i < 8; i++) {
            int idx = tid + i * 256;
            int p = idx >> 4, ch = idx & 15;
            *(uint4*)(ob + (size_t)p * 128 + ch * 8) = *(uint4*)(Os + p * 136 + ch * 8);
        }
        CP_WAIT0();
        __syncthreads();
    }
}

// == conv2: swizzled A (stride 256) + cp.async double-buffered B; 2 blocks/SM ====
#define C2_ZR   320
#define C2_B0o  82176
#define C2_B1o  (82176 + 16384)
#define C2_SMEM (82176 + 32768)        // 114944 -> 2 blocks/SM
__device__ __forceinline__ uint32_t c2sw(int row, int chunk) {
    return (uint32_t)(row * 256 + ((chunk ^ (row & 7)) << 4));
}
__global__ void __launch_bounds__(256, 2) hm_conv2(const __half* __restrict__ y1,
                                                   const __half* __restrict__ wh,
                                                   const float* __restrict__ bias,
                                                   float* __restrict__ pool) {
    extern __shared__ char smraw[];
    char* As = smraw;
    int tid = threadIdx.x, lane = tid & 31, warp = tid >> 5;
    int wm = warp & 3, wn = warp >> 2;   // 4M x 2N; warp tile 64px x 32oc
    int img = blockIdx.x;
    const __half* inb = y1 + (size_t)img * HW * 128;

    for (int i = 0; i < 21; i++) {
        int idx = tid + i * 256;
        if (idx < 321 * 16) {
            int hr = idx >> 4, c = idx & 15;
            int sy = -1 + (hr >> 5), sx = hr & 31;
            if (hr < 320 && sy >= 0)
                cpa16(As + c2sw(hr, c), inb + (size_t)(sy * 32 + sx) * 128 + c * 8);
            else
                *(uint4*)(As + c2sw(hr, c)) = make_uint4(0, 0, 0, 0);
        }
    }
    #pragma unroll
    for (int i = 0; i < 4; i++) {
        int idx = tid + i * 256;
        int row = idx >> 4, c = idx & 15;
        cpa16(smraw + C2_B0o + c2sw(row, c), wh + (size_t)row * 128 + c * 8);
    }
    CP_COMMIT(); CP_WAIT0(); __syncthreads();

    for (int q = 0; q < 4; q++) {
        float acc[4][4][4] = {};
        for (int tap = 0; tap < 9; tap++) {
            int k = q * 9 + tap;
            bool pf = (k < 35);
            if (pf) {
                int tn = (tap + 1) % 9;
                char* Bn = smraw + (((k + 1) & 1) ? C2_B1o : C2_B0o);
                const __half* wb = wh + (size_t)tn * 64 * 128;
                #pragma unroll
                for (int i = 0; i < 4; i++) {
                    int idx = tid + i * 256;
                    int row = idx >> 4, c = idx & 15;
                    cpa16(Bn + c2sw(row, c), wb + (size_t)row * 128 + c * 8);
                }
                CP_COMMIT();
            }
            char* Bcur = smraw + ((k & 1) ? C2_B1o : C2_B0o);
            int dy = tap / 3 - 1, dx = tap % 3 - 1;
            int hrow[4];
            #pragma unroll
            for (int mf = 0; mf < 4; mf++) {
                int p = wm * 64 + mf * 16 + (lane & 15);
                int py = p >> 5, px_ = p & 31;
                int sy = q * 8 + py + dy, sx = px_ + dx;
                hrow[mf] = ((unsigned)sy < (unsigned)HH && (unsigned)sx < (unsigned)WW)
                         ? (py + dy + 1) * 32 + sx : C2_ZR;
            }
            #pragma unroll
            for (int ks = 0; ks < 8; ks++) {
                uint32_t a[4][4], b[2][4];
                #pragma unroll
                for (int mf = 0; mf < 4; mf++)
                    ldsm4(a[mf], (const __half*)(As + c2sw(hrow[mf], ks * 2 + (lane >> 4))));
                #pragma unroll
                for (int nf2 = 0; nf2 < 2; nf2++) {
                    int n = wn * 32 + nf2 * 16 + (lane & 7) + (lane >> 4) * 8;
                    ldsm4(b[nf2], (const __half*)(Bcur + c2sw(n, ks * 2 + ((lane >> 3) & 1))));
                }
                #pragma unroll
                for (int mf = 0; mf < 4; mf++)
                    #pragma unroll
                    for (int nf = 0; nf < 4; nf++)
                        mma16816(acc[mf][nf], a[mf],
                                 b[nf >> 1][(nf & 1) * 2], b[nf >> 1][(nf & 1) * 2 + 1]);
            }
            if (pf) { CP_WAIT0(); }
            __syncthreads();
        }

        __half* os = (__half*)As;
        #pragma unroll
        for (int mf = 0; mf < 4; mf++) {
            #pragma unroll
            for (int nf = 0; nf < 4; nf++) {
                int px = wm * 64 + mf * 16 + (lane >> 2);
                int oc = wn * 32 + nf * 8 + 2 * (lane & 3);
                float bb0 = bias[oc], bb1 = bias[oc + 1];
                float v0 = fmaxf(acc[mf][nf][0] + bb0, 0.0f);
                float v1 = fmaxf(acc[mf][nf][1] + bb1, 0.0f);
                *(__half2*)(os + px * 80 + oc) = __floats2half2_rn(v0, v1);
                v0 = fmaxf(acc[mf][nf][2] + bb0, 0.0f);
                v1 = fmaxf(acc[mf][nf][3] + bb1, 0.0f);
                *(__half2*)(os + (px + 8) * 80 + oc) = __floats2half2_rn(v0, v1);
            }
        }
        __syncthreads();

        if (tid < 192) {
            int j = tid >> 6, c = tid & 63;
            int w0 = (j == 0) ? 0 : (j == 1 ? 10 : 21);
            int w1_ = (j == 0) ? 11 : (j == 1 ? 22 : 32);
            float cs0 = 0.0f, cs1 = 0.0f, cs2 = 0.0f;
            #pragma unroll
            for (int r = 0; r < 8; r++) {
                int y = q * 8 + r;
                float rs = 0.0f;
                for (int x = w0; x < w1_; x++) rs += __half2float(os[(r * 32 + x) * 80 + c]);
                if (y < 11) cs0 += rs;
                if (y >= 10 && y < 22) cs1 += rs;
                if (y >= 21) cs2 += rs;
            }
            float wsz = (float)(w1_ - w0);
            float* pb = pool + (size_t)img * 576 + c * 9 + j;
            if (q <= 1)           atomicAdd(pb + 0, cs0 / (11.0f * wsz));
            if (q == 1 || q == 2) atomicAdd(pb + 3, cs1 / (12.0f * wsz));
            if (q >= 2)           atomicAdd(pb + 6, cs2 / (11.0f * wsz));
        }
        __syncthreads();

        if (q < 3) {
            for (int i = 0; i < 21; i++) {
                int idx = tid + i * 256;
                if (idx < 321 * 16) {
                    int hr = idx >> 4, c = idx & 15;
                    int sy = (q + 1) * 8 - 1 + (hr >> 5), sx = hr & 31;
                    if (hr < 320 && sy >= 0 && sy < HH)
                        cpa16(As + c2sw(hr, c), inb + (size_t)(sy * 32 + sx) * 128 + c * 8);
                    else
                        *(uint4*)(As + c2sw(hr, c)) = make_uint4(0, 0, 0, 0);
                }
            }
            CP_COMMIT(); CP_WAIT0(); __syncthreads();
        }
    }
}

// ---------------- launch ----------------
extern "C" void kernel_launch(void* const* d_in, const int* in_sizes, int n_in,
                              void* d_out, int out_size) {
    const float* features = (const float*)d_in[0];
    const float* cell     = (const float*)d_in[1];
    const float* gaze     = (const float*)d_in[2];
    const float* w1  = (const float*)d_in[3];
    const float* b1  = (const float*)d_in[4];
    const float* w2  = (const float*)d_in[5];
    const float* b2  = (const float*)d_in[6];
    const float* wvw = (const float*)d_in[7];
    const float* bv  = (const float*)d_in[8];
    const float* ws1 = (const float*)d_in[9];
    const float* bs1 = (const float*)d_in[10];
    const float* ws2 = (const float*)d_in[11];
    const float* bs2 = (const float*)d_in[12];
    const float* ck1 = (const float*)d_in[13];
    const float* cb1 = (const float*)d_in[14];
    const float* ck2 = (const float*)d_in[15];
    const float* cb2 = (const float*)d_in[16];
    const float* wo  = (const float*)d_in[17];
    const float* bo  = (const float*)d_in[18];

    float* out = (float*)d_out;
    float* updated = out + OUT0;

    float *px, *ph1, *ph2, *pwv, *ppool;
    __half *puph, *pwh1, *pwh2, *py1h;
    cudaGetSymbolAddress((void**)&px,   g_x);
    cudaGetSymbolAddress((void**)&ph1,  g_h1);
    cudaGetSymbolAddress((void**)&ph2,  g_h2);
    cudaGetSymbolAddress((void**)&pwv,  g_wv);
    cudaGetSymbolAddress((void**)&puph, g_uph);
    cudaGetSymbolAddress((void**)&pwh1, g_wh1);
    cudaGetSymbolAddress((void**)&pwh2, g_wh2);
    cudaGetSymbolAddress((void**)&py1h, g_y1h);
    cudaGetSymbolAddress((void**)&ppool,g_pool);

    // 0) x = [features, pe]
    build_x_kernel<<<(BATCH * 576 + 255) / 256, 256>>>(features, gaze, px);

    // 1) MLP1 (576 -> 256, relu) via HMMA
    {
        dim3 g(BATCH / 128, 256 / 64);
        hgemm_kernel<true><<<g, 256>>>(px, w1, b1, ph1, 576, 256);
    }
    // 2) MLP2 (256 -> 128, relu) via HMMA
    {
        dim3 g(BATCH / 128, 128 / 64);
        hgemm_kernel<true><<<g, 256>>>(ph1, w2, b2, ph2, 256, 128);
    }
    // 3) write-values GEMM (128 -> 1936) via HMMA
    {
        dim3 g(BATCH / 128, (1936 + 63) / 64);
        hgemm_kernel<false><<<g, 256>>>(ph2, wvw, bv, pwv, 128, 1936);
    }

    // 4) gate + scatter (+ weight prep + pool zero) -> updated + fp16 copy
    {
        size_t smem = (size_t)(1024 * 17 + 1024 + 2048 + 128) * sizeof(float);
        cudaFuncSetAttribute(gate_scatter_kernel,
                             cudaFuncAttributeMaxDynamicSharedMemorySize, (int)smem);
        gate_scatter_kernel<<<BATCH, 256, smem>>>(cell, gaze, pwv, ws1, bs1, ws2, bs2,
                                                  ck1, ck2, pwh1, pwh2, ppool,
                                                  updated, puph);
    }

    // 5) conv1 persistent (per image)
    {
        cudaFuncSetAttribute(hm_conv1, cudaFuncAttributeMaxDynamicSharedMemorySize, C1_SMEM);
        hm_conv1<<<BATCH, 256, C1_SMEM>>>(puph, pwh1, cb1, py1h);
    }
    // 6) conv2: swizzled A + async-double-buffered B, 2 blocks/SM, fused pool
    {
        cudaFuncSetAttribute(hm_conv2, cudaFuncAttributeMaxDynamicSharedMemorySize, C2_SMEM);
        hm_conv2<<<BATCH, 256, C2_SMEM>>>(py1h, pwh2, cb2, ppool);
    }

    // 7) final linear (576 -> 576) via HMMA
    {
        dim3 g(BATCH / 128, 576 / 64);
        hgemm_kernel<false><<<g, 256>>>(ppool, wo, bo, out, 576, 576);
    }
}